// round 14
// baseline (speedup 1.0000x reference)
#include <cuda_runtime.h>
#include <cuda_fp16.h>
#include <cstdint>

#define B_  2
#define S_  2048
#define D_  4096
#define H_  32
#define HD_ 128
#define MTOK (B_*S_)
#define NELEM ((size_t)MTOK * D_)

// ---------------- scratch (allocation-free) ----------------
__device__ __half g_x[NELEM];
__device__ __half g_wq[NELEM], g_wk[NELEM], g_wv[NELEM], g_wo[NELEM];
__device__ __half g_q[NELEM], g_k[NELEM], g_v[NELEM], g_a[NELEM];

// ---------------- helpers ----------------
__device__ __forceinline__ uint32_t smem_u32(const void* p) {
    return (uint32_t)__cvta_generic_to_shared(p);
}
__device__ __forceinline__ void cp16(void* dst, const void* src) {
    asm volatile("cp.async.cg.shared.global [%0], [%1], 16;"
                 :: "r"(smem_u32(dst)), "l"(src) : "memory");
}
__device__ __forceinline__ void cp_commit() {
    asm volatile("cp.async.commit_group;" ::: "memory");
}
template<int N>
__device__ __forceinline__ void cp_wait() {
    asm volatile("cp.async.wait_group %0;" :: "n"(N) : "memory");
}
__device__ __forceinline__ void ldm_x4(uint32_t& r0, uint32_t& r1, uint32_t& r2, uint32_t& r3, uint32_t addr) {
    asm volatile("ldmatrix.sync.aligned.m8n8.x4.shared.b16 {%0,%1,%2,%3}, [%4];"
                 : "=r"(r0), "=r"(r1), "=r"(r2), "=r"(r3) : "r"(addr));
}
__device__ __forceinline__ void ldm_x4_t(uint32_t& r0, uint32_t& r1, uint32_t& r2, uint32_t& r3, uint32_t addr) {
    asm volatile("ldmatrix.sync.aligned.m8n8.x4.trans.shared.b16 {%0,%1,%2,%3}, [%4];"
                 : "=r"(r0), "=r"(r1), "=r"(r2), "=r"(r3) : "r"(addr));
}
__device__ __forceinline__ void mma_f16(float* c, const uint32_t* a, const uint32_t* b) {
    asm volatile(
        "mma.sync.aligned.m16n8k16.row.col.f32.f16.f16.f32 "
        "{%0,%1,%2,%3}, {%4,%5,%6,%7}, {%8,%9}, {%0,%1,%2,%3};"
        : "+f"(c[0]), "+f"(c[1]), "+f"(c[2]), "+f"(c[3])
        : "r"(a[0]), "r"(a[1]), "r"(a[2]), "r"(a[3]), "r"(b[0]), "r"(b[1]));
}
__device__ __forceinline__ uint32_t pack_h2(float a, float b) {
    __half2 h = __floats2half2_rn(a, b);
    return *(uint32_t*)&h;
}

// ---------------- convert: fp32 -> fp16, 5 tensors, 4 chunks/thread (MLP=4) ----------------
#define CVT_PER_THREAD 4
__global__ void cvt_h5(const float4* __restrict__ s0, const float4* __restrict__ s1,
                       const float4* __restrict__ s2, const float4* __restrict__ s3,
                       const float4* __restrict__ s4,
                       uint2* __restrict__ d0, uint2* __restrict__ d1,
                       uint2* __restrict__ d2, uint2* __restrict__ d3,
                       uint2* __restrict__ d4, int n4) {
    const int stride = (int)gridDim.x * (int)blockDim.x;
    const int base = blockIdx.x * blockDim.x + threadIdx.x;
    const int z = blockIdx.y;
    const float4* s = (z == 0) ? s0 : (z == 1) ? s1 : (z == 2) ? s2 : (z == 3) ? s3 : s4;
    uint2* d = (z == 0) ? d0 : (z == 1) ? d1 : (z == 2) ? d2 : (z == 3) ? d3 : d4;

    float4 v[CVT_PER_THREAD];
#pragma unroll
    for (int p = 0; p < CVT_PER_THREAD; p++) {
        const int i = base + p * stride;
        if (i < n4) v[p] = s[i];
    }
#pragma unroll
    for (int p = 0; p < CVT_PER_THREAD; p++) {
        const int i = base + p * stride;
        if (i < n4) d[i] = make_uint2(pack_h2(v[p].x, v[p].y), pack_h2(v[p].z, v[p].w));
    }
}

// ============ GEMM: 128x256x32 CTA tile, 8 warps (2x4), warp tile 64x64, frag-pipelined ============
#define GBM 128
#define GBN 256
#define GBK 32
#define GLD 40
#define SA_ELEMS (GBM * GLD)              // 5120 halves (A slab)
#define SB_ELEMS (GBN * GLD)              // 10240 halves (B slab)
#define STAGE_ELEMS (SA_ELEMS + SB_ELEMS) // 15360 halves = 30720 B
#define GEMM_SMEM (4 * STAGE_ELEMS * 2)   // 122880 B
#define GT 256

__device__ __forceinline__ void ldm_frags(
    const __half* sA, const __half* sB, int wm, int wn, int lrow, int lcol8,
    int kc, uint32_t a[4][4], uint32_t b[8][2]) {
    const int col = kc * 16 + lcol8;
#pragma unroll
    for (int mt = 0; mt < 4; mt++) {
        const int row = wm * 64 + mt * 16 + lrow;
        ldm_x4(a[mt][0], a[mt][1], a[mt][2], a[mt][3],
               smem_u32(sA + row * GLD + col));
    }
#pragma unroll
    for (int nt2 = 0; nt2 < 4; nt2++) {
        const int row = wn * 64 + nt2 * 16 + lrow;
        uint32_t r0, r1, r2, r3;
        ldm_x4(r0, r1, r2, r3, smem_u32(sB + row * GLD + col));
        b[2*nt2][0] = r0; b[2*nt2][1] = r2;
        b[2*nt2+1][0] = r1; b[2*nt2+1][1] = r3;
    }
}

__device__ __forceinline__ void gemm_main(
    float acc[4][8][4], const __half* __restrict__ Ag, const __half* __restrict__ Bg,
    int m0, int n0, __half* sm, int tid, int wm, int wn, int lrow, int lcol8) {

    auto load_stage = [&](int kb, int buf) {
        __half* base = sm + buf * STAGE_ELEMS;
        const int k0 = kb * GBK;
#pragma unroll
        for (int p = 0; p < 6; p++) {
            const int t = tid + p * GT;           // 0..1535
            if (t < 512) {                        // A: 512 chunks
                const int row = t >> 2, col8 = (t & 3) << 3;
                cp16(base + row * GLD + col8,
                     Ag + (size_t)(m0 + row) * D_ + k0 + col8);
            } else {                              // B: 1024 chunks
                const int t2 = t - 512;
                const int row = t2 >> 2, col8 = (t2 & 3) << 3;
                cp16(base + SA_ELEMS + row * GLD + col8,
                     Bg + (size_t)(n0 + row) * D_ + k0 + col8);
            }
        }
    };

    const int KT = D_ / GBK;           // 128
    load_stage(0, 0); cp_commit();
    load_stage(1, 1); cp_commit();
    load_stage(2, 2); cp_commit();
    cp_wait<1>();                      // stages 0 and 1 landed
    __syncthreads();

    uint32_t a0[4][4], b0[8][2], a1[4][4], b1[8][2];
    ldm_frags(sm, sm + SA_ELEMS, wm, wn, lrow, lcol8, 0, a0, b0);

    for (int kb = 0; kb < KT; kb++) {
        const __half* sA = sm + (kb & 3) * STAGE_ELEMS;
        const __half* sB = sA + SA_ELEMS;
        if (kb + 3 < KT) load_stage(kb + 3, (kb + 3) & 3);
        cp_commit();

        ldm_frags(sA, sB, wm, wn, lrow, lcol8, 1, a1, b1);

#pragma unroll
        for (int mt = 0; mt < 4; mt++)
#pragma unroll
            for (int nt = 0; nt < 8; nt++)
                mma_f16(acc[mt][nt], a0[mt], b0[nt]);

        if (kb + 1 < KT) {
            const __half* nA = sm + ((kb + 1) & 3) * STAGE_ELEMS;
            ldm_frags(nA, nA + SA_ELEMS, wm, wn, lrow, lcol8, 0, a0, b0);
        }

#pragma unroll
        for (int mt = 0; mt < 4; mt++)
#pragma unroll
            for (int nt = 0; nt < 8; nt++)
                mma_f16(acc[mt][nt], a1[mt], b1[nt]);

        cp_wait<1>();
        __syncthreads();
    }
}

// ---- fused QKV GEMM: z=0 -> q (rope), z=1 -> k (rope), z=2 -> v (plain fp16) ----
__global__ __launch_bounds__(GT, 1)
void qkv_gemm(const __half* __restrict__ Ag,
              const __half* __restrict__ W0, const __half* __restrict__ W1,
              const __half* __restrict__ W2,
              __half* __restrict__ C0, __half* __restrict__ C1, __half* __restrict__ C2,
              const float* __restrict__ fc, const float* __restrict__ fs) {
    extern __shared__ __align__(16) __half sm[];
    const int tid = threadIdx.x;
    const int wid = tid >> 5, lane = tid & 31;
    const int wm = wid >> 2, wn = wid & 3;        // 2x4 warp grid, warp tile 64x64
    const int m0 = blockIdx.x * GBM, n0 = blockIdx.y * GBN;
    const int lrow = lane & 15, lcol8 = (lane >> 4) << 3;
    const int g = lane >> 2, tq = lane & 3;
    const int z = blockIdx.z;
    const __half* Bg = (z == 0) ? W0 : (z == 1) ? W1 : W2;
    __half* Ch = (z == 0) ? C0 : (z == 1) ? C1 : C2;
    const bool dorope = (z < 2);

    float acc[4][8][4];
#pragma unroll
    for (int i = 0; i < 4; i++)
#pragma unroll
        for (int j = 0; j < 8; j++)
#pragma unroll
            for (int e = 0; e < 4; e++) acc[i][j][e] = 0.f;

    gemm_main(acc, Ag, Bg, m0, n0, sm, tid, wm, wn, lrow, lcol8);

#pragma unroll
    for (int mt = 0; mt < 4; mt++)
#pragma unroll
        for (int nt = 0; nt < 8; nt++) {
            const int row0 = m0 + wm * 64 + mt * 16 + g;
            const int col  = n0 + wn * 64 + nt * 8 + tq * 2;
            if (dorope) {
                const int i = (col & (HD_ - 1)) >> 1;
#pragma unroll
                for (int half = 0; half < 2; half++) {
                    const int row = row0 + half * 8;
                    const int s = row & (S_ - 1);
                    const float c = fc[s * (HD_/2) + i];
                    const float sn = fs[s * (HD_/2) + i];
                    const float x0 = acc[mt][nt][2*half], x1 = acc[mt][nt][2*half+1];
                    *(uint32_t*)(Ch + (size_t)row * D_ + col) =
                        pack_h2(x0 * c - x1 * sn, x0 * sn + x1 * c);
                }
            } else {
                *(uint32_t*)(Ch + (size_t)row0 * D_ + col) =
                    pack_h2(acc[mt][nt][0], acc[mt][nt][1]);
                *(uint32_t*)(Ch + (size_t)(row0 + 8) * D_ + col) =
                    pack_h2(acc[mt][nt][2], acc[mt][nt][3]);
            }
        }
}

// ---- output-projection GEMM: fp32 C ----
__global__ __launch_bounds__(GT, 1)
void gemm_out(const __half* __restrict__ Ag, const __half* __restrict__ Bg,
              float* __restrict__ C) {
    extern __shared__ __align__(16) __half sm[];
    const int tid = threadIdx.x;
    const int wid = tid >> 5, lane = tid & 31;
    const int wm = wid >> 2, wn = wid & 3;
    const int m0 = blockIdx.x * GBM, n0 = blockIdx.y * GBN;
    const int lrow = lane & 15, lcol8 = (lane >> 4) << 3;
    const int g = lane >> 2, tq = lane & 3;

    float acc[4][8][4];
#pragma unroll
    for (int i = 0; i < 4; i++)
#pragma unroll
        for (int j = 0; j < 8; j++)
#pragma unroll
            for (int e = 0; e < 4; e++) acc[i][j][e] = 0.f;

    gemm_main(acc, Ag, Bg, m0, n0, sm, tid, wm, wn, lrow, lcol8);

#pragma unroll
    for (int mt = 0; mt < 4; mt++)
#pragma unroll
        for (int nt = 0; nt < 8; nt++) {
            const int row0 = m0 + wm * 64 + mt * 16 + g;
            const int col  = n0 + wn * 64 + nt * 8 + tq * 2;
            *(float2*)(C + (size_t)row0 * D_ + col) =
                make_float2(acc[mt][nt][0], acc[mt][nt][1]);
            *(float2*)(C + (size_t)(row0 + 8) * D_ + col) =
                make_float2(acc[mt][nt][2], acc[mt][nt][3]);
        }
}

// ---------------- flash attention (round-10, unchanged) ----------------
#define ALD 136
#define AQ_ELEMS (128 * ALD)
#define AKV_ELEMS (64 * ALD)
#define ATTN_SMEM ((AQ_ELEMS + 2 * 2 * AKV_ELEMS) * 2)   // 104448 B

__global__ __launch_bounds__(256, 1)
void attn_kernel(const __half* __restrict__ Q, const __half* __restrict__ Kg,
                 const __half* __restrict__ Vg, __half* __restrict__ O) {
    extern __shared__ __align__(16) __half smn[];
    __half* sQ = smn;
    __half* sKV = sQ + AQ_ELEMS;

    const int tid = threadIdx.x;
    const int wid = tid >> 5, lane = tid & 31;
    const int g = lane >> 2, tq = lane & 3;
    const int qt = (int)gridDim.x - 1 - (int)blockIdx.x;
    const int h = blockIdx.y, b = blockIdx.z;
    const int lrow = lane & 15, lcol8 = (lane >> 4) << 3;
    const float scale = 0.08838834764831845f;

    auto load_kv = [&](int j, int buf) {
        __half* base = sKV + buf * 2 * AKV_ELEMS;
#pragma unroll
        for (int p = 0; p < 8; p++) {
            int c = tid + p * 256;
            int arr = c >> 10;
            int idx = c & 1023;
            int row = idx >> 4;
            int col8 = (idx & 15) << 3;
            size_t goff = ((size_t)(b * S_ + j * 64 + row)) * D_ + h * HD_ + col8;
            cp16(base + arr * AKV_ELEMS + row * ALD + col8, (arr ? Vg : Kg) + goff);
        }
    };

    {
#pragma unroll
        for (int p = 0; p < 8; p++) {
            int c = tid + p * 256;
            int row = c >> 4;
            int col8 = (c & 15) << 3;
            size_t goff = ((size_t)(b * S_ + qt * 128 + row)) * D_ + h * HD_ + col8;
            cp16(sQ + row * ALD + col8, Q + goff);
        }
    }
    load_kv(0, 0);
    cp_commit();

    float oacc[16][4];
#pragma unroll
    for (int i = 0; i < 16; i++)
#pragma unroll
        for (int e = 0; e < 4; e++) oacc[i][e] = 0.f;
    float sm2[2] = {-1e30f, -1e30f};
    float sl2[2] = {0.f, 0.f};

    const int qrow = wid * 16 + lrow;
    const int jmax = 2 * qt + 1;
    for (int j = 0; j <= jmax; ++j) {
        cp_wait<0>();
        __syncthreads();
        if (j + 1 <= jmax) load_kv(j + 1, (j + 1) & 1);
        cp_commit();

        const __half* sK = sKV + (j & 1) * 2 * AKV_ELEMS;
        const __half* sV = sK + AKV_ELEMS;

        float sacc[8][4];
#pragma unroll
        for (int i = 0; i < 8; i++)
#pragma unroll
            for (int e = 0; e < 4; e++) sacc[i][e] = 0.f;

        uint32_t qf[2][4], kr[2][4];
        ldm_x4(qf[0][0], qf[0][1], qf[0][2], qf[0][3],
               smem_u32(sQ + qrow * ALD + lcol8));
        ldm_x4(kr[0][0], kr[0][1], kr[0][2], kr[0][3],
               smem_u32(sK + lrow * ALD + lcol8));

#pragma unroll
        for (int kc = 0; kc < 8; kc++) {
            const int cq = kc & 1;
#pragma unroll
            for (int nt2 = 0; nt2 < 4; nt2++) {
                const int s = kc * 4 + nt2;
                const int cur = s & 1, alt = cur ^ 1;
                if (s < 31) {
                    const int ns = s + 1, nkc = ns >> 2, nnt2 = ns & 3;
                    ldm_x4(kr[alt][0], kr[alt][1], kr[alt][2], kr[alt][3],
                           smem_u32(sK + (nnt2 * 16 + lrow) * ALD + nkc * 16 + lcol8));
                }
                if (nt2 == 3 && kc < 7) {
                    ldm_x4(qf[cq ^ 1][0], qf[cq ^ 1][1], qf[cq ^ 1][2], qf[cq ^ 1][3],
                           smem_u32(sQ + qrow * ALD + (kc + 1) * 16 + lcol8));
                }
                uint32_t b0[2] = {kr[cur][0], kr[cur][2]};
                uint32_t b1[2] = {kr[cur][1], kr[cur][3]};
                mma_f16(sacc[2*nt2], qf[cq], b0);
                mma_f16(sacc[2*nt2+1], qf[cq], b1);
            }
        }

        const int qg0 = qt * 128 + wid * 16 + g;
        const bool need_mask = (j >= 2 * qt);
        float mx0 = -1e30f, mx1 = -1e30f;
#pragma unroll
        for (int nt = 0; nt < 8; nt++) {
            int kg = j * 64 + nt * 8 + tq * 2;
#pragma unroll
            for (int e = 0; e < 4; e++) {
                float sv = sacc[nt][e] * scale;
                int row = (e < 2) ? qg0 : (qg0 + 8);
                int col = kg + (e & 1);
                if (need_mask && col > row) sv = -1e30f;
                sacc[nt][e] = sv;
                if (e < 2) mx0 = fmaxf(mx0, sv); else mx1 = fmaxf(mx1, sv);
            }
        }
        mx0 = fmaxf(mx0, __shfl_xor_sync(0xffffffffu, mx0, 1));
        mx0 = fmaxf(mx0, __shfl_xor_sync(0xffffffffu, mx0, 2));
        mx1 = fmaxf(mx1, __shfl_xor_sync(0xffffffffu, mx1, 1));
        mx1 = fmaxf(mx1, __shfl_xor_sync(0xffffffffu, mx1, 2));

        float mn0 = fmaxf(sm2[0], mx0), mn1 = fmaxf(sm2[1], mx1);
        float al0 = __expf(sm2[0] - mn0), al1 = __expf(sm2[1] - mn1);
        sm2[0] = mn0; sm2[1] = mn1;

        float rs0 = 0.f, rs1 = 0.f;
#pragma unroll
        for (int nt = 0; nt < 8; nt++)
#pragma unroll
            for (int e = 0; e < 4; e++) {
                float pv = __expf(sacc[nt][e] - ((e < 2) ? mn0 : mn1));
                sacc[nt][e] = pv;
                if (e < 2) rs0 += pv; else rs1 += pv;
            }
        rs0 += __shfl_xor_sync(0xffffffffu, rs0, 1);
        rs0 += __shfl_xor_sync(0xffffffffu, rs0, 2);
        rs1 += __shfl_xor_sync(0xffffffffu, rs1, 1);
        rs1 += __shfl_xor_sync(0xffffffffu, rs1, 2);
        sl2[0] = sl2[0] * al0 + rs0;
        sl2[1] = sl2[1] * al1 + rs1;

#pragma unroll
        for (int dt = 0; dt < 16; dt++) {
            oacc[dt][0] *= al0; oacc[dt][1] *= al0;
            oacc[dt][2] *= al1; oacc[dt][3] *= al1;
        }

        uint32_t pf[4][4];
#pragma unroll
        for (int kc = 0; kc < 4; kc++) {
            pf[kc][0] = pack_h2(sacc[2*kc][0],   sacc[2*kc][1]);
            pf[kc][1] = pack_h2(sacc[2*kc][2],   sacc[2*kc][3]);
            pf[kc][2] = pack_h2(sacc[2*kc+1][0], sacc[2*kc+1][1]);
            pf[kc][3] = pack_h2(sacc[2*kc+1][2], sacc[2*kc+1][3]);
        }

        uint32_t vr[2][4];
        ldm_x4_t(vr[0][0], vr[0][1], vr[0][2], vr[0][3],
                 smem_u32(sV + lrow * ALD + lcol8));
#pragma unroll
        for (int s = 0; s < 32; s++) {
            const int kc = s >> 3, dt2 = s & 7;
            const int cur = s & 1, alt = cur ^ 1;
            if (s < 31) {
                const int ns = s + 1, nkc = ns >> 3, ndt2 = ns & 7;
                ldm_x4_t(vr[alt][0], vr[alt][1], vr[alt][2], vr[alt][3],
                         smem_u32(sV + (nkc * 16 + lrow) * ALD + ndt2 * 16 + lcol8));
            }
            uint32_t v0[2] = {vr[cur][0], vr[cur][1]};
            uint32_t v1[2] = {vr[cur][2], vr[cur][3]};
            mma_f16(oacc[2*dt2], pf[kc], v0);
            mma_f16(oacc[2*dt2+1], pf[kc], v1);
        }
    }

    float inv0 = 1.f / sl2[0];
    float inv1 = 1.f / sl2[1];
    int s0r = qt * 128 + wid * 16 + g;
#pragma unroll
    for (int dt = 0; dt < 16; dt++) {
        int col = h * HD_ + dt * 8 + tq * 2;
        *(uint32_t*)(O + ((size_t)(b * S_ + s0r)) * D_ + col) =
            pack_h2(oacc[dt][0] * inv0, oacc[dt][1] * inv0);
        *(uint32_t*)(O + ((size_t)(b * S_ + s0r + 8)) * D_ + col) =
            pack_h2(oacc[dt][2] * inv1, oacc[dt][3] * inv1);
    }
}

// ---------------- launch ----------------
extern "C" void kernel_launch(void* const* d_in, const int* in_sizes, int n_in,
                              void* d_out, int out_size) {
    const float* x  = (const float*)d_in[0];
    const float* fc = (const float*)d_in[1];
    const float* fs = (const float*)d_in[2];
    const float* wq = (const float*)d_in[4];
    const float* wk = (const float*)d_in[5];
    const float* wv = (const float*)d_in[6];
    const float* wo = (const float*)d_in[7];
    float* out = (float*)d_out;

    __half *xh, *wqh, *wkh, *wvh, *woh, *qh, *kh, *vh, *ah;
    cudaGetSymbolAddress((void**)&xh, g_x);
    cudaGetSymbolAddress((void**)&wqh, g_wq);
    cudaGetSymbolAddress((void**)&wkh, g_wk);
    cudaGetSymbolAddress((void**)&wvh, g_wv);
    cudaGetSymbolAddress((void**)&woh, g_wo);
    cudaGetSymbolAddress((void**)&qh, g_q);
    cudaGetSymbolAddress((void**)&kh, g_k);
    cudaGetSymbolAddress((void**)&vh, g_v);
    cudaGetSymbolAddress((void**)&ah, g_a);

    const int n4 = (int)(NELEM / 4);
    const int cvt_blocks = (n4 / CVT_PER_THREAD + 255) / 256;
    cvt_h5<<<dim3(cvt_blocks, 5), 256>>>(
        (const float4*)x, (const float4*)wq, (const float4*)wk,
        (const float4*)wv, (const float4*)wo,
        (uint2*)xh, (uint2*)wqh, (uint2*)wkh, (uint2*)wvh, (uint2*)woh, n4);

    cudaFuncSetAttribute(qkv_gemm, cudaFuncAttributeMaxDynamicSharedMemorySize, GEMM_SMEM);
    cudaFuncSetAttribute(gemm_out, cudaFuncAttributeMaxDynamicSharedMemorySize, GEMM_SMEM);

    dim3 gq(MTOK / GBM, D_ / GBN, 3);   // (32, 16, 3)
    qkv_gemm<<<gq, GT, GEMM_SMEM>>>(xh, wqh, wkh, wvh, qh, kh, vh, fc, fs);

    cudaFuncSetAttribute(attn_kernel, cudaFuncAttributeMaxDynamicSharedMemorySize, ATTN_SMEM);
    attn_kernel<<<dim3(S_ / 128, H_, B_), 256, ATTN_SMEM>>>(qh, kh, vh, ah);

    dim3 gg(MTOK / GBM, D_ / GBN);      // (32, 16)
    gemm_out<<<gg, GT, GEMM_SMEM>>>(ah, woh, out);
}

// round 15
// speedup vs baseline: 1.0130x; 1.0130x over previous
#include <cuda_runtime.h>
#include <cuda_fp16.h>
#include <cstdint>

#define B_  2
#define S_  2048
#define D_  4096
#define H_  32
#define HD_ 128
#define MTOK (B_*S_)
#define NELEM ((size_t)MTOK * D_)

// ---------------- scratch (allocation-free) ----------------
__device__ __half g_x[NELEM];
__device__ __half g_wq[NELEM], g_wk[NELEM], g_wv[NELEM], g_wo[NELEM];
__device__ __half g_q[NELEM], g_k[NELEM], g_v[NELEM], g_a[NELEM];

// ---------------- helpers ----------------
__device__ __forceinline__ uint32_t smem_u32(const void* p) {
    return (uint32_t)__cvta_generic_to_shared(p);
}
__device__ __forceinline__ void cp16(void* dst, const void* src) {
    asm volatile("cp.async.cg.shared.global [%0], [%1], 16;"
                 :: "r"(smem_u32(dst)), "l"(src) : "memory");
}
__device__ __forceinline__ void cp_commit() {
    asm volatile("cp.async.commit_group;" ::: "memory");
}
template<int N>
__device__ __forceinline__ void cp_wait() {
    asm volatile("cp.async.wait_group %0;" :: "n"(N) : "memory");
}
__device__ __forceinline__ void ldm_x4(uint32_t& r0, uint32_t& r1, uint32_t& r2, uint32_t& r3, uint32_t addr) {
    asm volatile("ldmatrix.sync.aligned.m8n8.x4.shared.b16 {%0,%1,%2,%3}, [%4];"
                 : "=r"(r0), "=r"(r1), "=r"(r2), "=r"(r3) : "r"(addr));
}
__device__ __forceinline__ void ldm_x4_t(uint32_t& r0, uint32_t& r1, uint32_t& r2, uint32_t& r3, uint32_t addr) {
    asm volatile("ldmatrix.sync.aligned.m8n8.x4.trans.shared.b16 {%0,%1,%2,%3}, [%4];"
                 : "=r"(r0), "=r"(r1), "=r"(r2), "=r"(r3) : "r"(addr));
}
__device__ __forceinline__ void mma_f16(float* c, const uint32_t* a, const uint32_t* b) {
    asm volatile(
        "mma.sync.aligned.m16n8k16.row.col.f32.f16.f16.f32 "
        "{%0,%1,%2,%3}, {%4,%5,%6,%7}, {%8,%9}, {%0,%1,%2,%3};"
        : "+f"(c[0]), "+f"(c[1]), "+f"(c[2]), "+f"(c[3])
        : "r"(a[0]), "r"(a[1]), "r"(a[2]), "r"(a[3]), "r"(b[0]), "r"(b[1]));
}
__device__ __forceinline__ uint32_t pack_h2(float a, float b) {
    __half2 h = __floats2half2_rn(a, b);
    return *(uint32_t*)&h;
}

// ---------------- convert: fp32 -> fp16, 5 tensors, 4 chunks/thread (MLP=4) ----------------
#define CVT_PER_THREAD 4
__global__ void cvt_h5(const float4* __restrict__ s0, const float4* __restrict__ s1,
                       const float4* __restrict__ s2, const float4* __restrict__ s3,
                       const float4* __restrict__ s4,
                       uint2* __restrict__ d0, uint2* __restrict__ d1,
                       uint2* __restrict__ d2, uint2* __restrict__ d3,
                       uint2* __restrict__ d4, int n4) {
    const int stride = (int)gridDim.x * (int)blockDim.x;
    const int base = blockIdx.x * blockDim.x + threadIdx.x;
    const int z = blockIdx.y;
    const float4* s = (z == 0) ? s0 : (z == 1) ? s1 : (z == 2) ? s2 : (z == 3) ? s3 : s4;
    uint2* d = (z == 0) ? d0 : (z == 1) ? d1 : (z == 2) ? d2 : (z == 3) ? d3 : d4;

    float4 v[CVT_PER_THREAD];
#pragma unroll
    for (int p = 0; p < CVT_PER_THREAD; p++) {
        const int i = base + p * stride;
        if (i < n4) v[p] = s[i];
    }
#pragma unroll
    for (int p = 0; p < CVT_PER_THREAD; p++) {
        const int i = base + p * stride;
        if (i < n4) d[i] = make_uint2(pack_h2(v[p].x, v[p].y), pack_h2(v[p].z, v[p].w));
    }
}

// ============ GEMM: 128x128x32 CTA tile, 4 warps, warp tile 64x64, frag-pipelined ============
// (round-13 configuration, verbatim — FROZEN)
#define GBM 128
#define GBN 128
#define GBK 32
#define GLD 40
#define SA_ELEMS (GBM * GLD)          // 5120 halves
#define STAGE_ELEMS (2 * SA_ELEMS)    // 20KB
#define GEMM_SMEM (4 * STAGE_ELEMS * 2)   // 80KB
#define GT 128

__device__ __forceinline__ void ldm_frags(
    const __half* sA, const __half* sB, int wm, int wn, int lrow, int lcol8,
    int kc, uint32_t a[4][4], uint32_t b[8][2]) {
    const int col = kc * 16 + lcol8;
#pragma unroll
    for (int mt = 0; mt < 4; mt++) {
        const int row = wm * 64 + mt * 16 + lrow;
        ldm_x4(a[mt][0], a[mt][1], a[mt][2], a[mt][3],
               smem_u32(sA + row * GLD + col));
    }
#pragma unroll
    for (int nt2 = 0; nt2 < 4; nt2++) {
        const int row = wn * 64 + nt2 * 16 + lrow;
        uint32_t r0, r1, r2, r3;
        ldm_x4(r0, r1, r2, r3, smem_u32(sB + row * GLD + col));
        b[2*nt2][0] = r0; b[2*nt2][1] = r2;
        b[2*nt2+1][0] = r1; b[2*nt2+1][1] = r3;
    }
}

__device__ __forceinline__ void gemm_main(
    float acc[4][8][4], const __half* __restrict__ Ag, const __half* __restrict__ Bg,
    int m0, int n0, __half* sm, int tid, int wm, int wn, int lrow, int lcol8) {

    auto load_stage = [&](int kb, int buf) {
        __half* base = sm + buf * STAGE_ELEMS;
        const int k0 = kb * GBK;
#pragma unroll
        for (int p = 0; p < 8; p++) {
            const int t = tid + p * GT;
            const int arr = t >> 9;
            const int i = t & 511;
            const int row = i >> 2, col8 = (i & 3) << 3;
            const __half* gsrc = (arr ? Bg : Ag) + (size_t)((arr ? n0 : m0) + row) * D_ + k0 + col8;
            cp16(base + arr * SA_ELEMS + row * GLD + col8, gsrc);
        }
    };

    const int KT = D_ / GBK;           // 128
    load_stage(0, 0); cp_commit();
    load_stage(1, 1); cp_commit();
    load_stage(2, 2); cp_commit();
    cp_wait<1>();
    __syncthreads();

    uint32_t a0[4][4], b0[8][2], a1[4][4], b1[8][2];
    ldm_frags(sm, sm + SA_ELEMS, wm, wn, lrow, lcol8, 0, a0, b0);

    for (int kb = 0; kb < KT; kb++) {
        const __half* sA = sm + (kb & 3) * STAGE_ELEMS;
        const __half* sB = sA + SA_ELEMS;
        if (kb + 3 < KT) load_stage(kb + 3, (kb + 3) & 3);
        cp_commit();

        ldm_frags(sA, sB, wm, wn, lrow, lcol8, 1, a1, b1);

#pragma unroll
        for (int mt = 0; mt < 4; mt++)
#pragma unroll
            for (int nt = 0; nt < 8; nt++)
                mma_f16(acc[mt][nt], a0[mt], b0[nt]);

        if (kb + 1 < KT) {
            const __half* nA = sm + ((kb + 1) & 3) * STAGE_ELEMS;
            ldm_frags(nA, nA + SA_ELEMS, wm, wn, lrow, lcol8, 0, a0, b0);
        }

#pragma unroll
        for (int mt = 0; mt < 4; mt++)
#pragma unroll
            for (int nt = 0; nt < 8; nt++)
                mma_f16(acc[mt][nt], a1[mt], b1[nt]);

        cp_wait<1>();
        __syncthreads();
    }
}

// ---- fused QKV GEMM: z=0 -> q (rope), z=1 -> k (rope), z=2 -> v (plain fp16) ----
__global__ __launch_bounds__(GT, 2)
void qkv_gemm(const __half* __restrict__ Ag,
              const __half* __restrict__ W0, const __half* __restrict__ W1,
              const __half* __restrict__ W2,
              __half* __restrict__ C0, __half* __restrict__ C1, __half* __restrict__ C2,
              const float* __restrict__ fc, const float* __restrict__ fs) {
    extern __shared__ __align__(16) __half sm[];
    const int tid = threadIdx.x;
    const int wid = tid >> 5, lane = tid & 31;
    const int wm = wid >> 1, wn = wid & 1;
    const int m0 = blockIdx.x * GBM, n0 = blockIdx.y * GBN;
    const int lrow = lane & 15, lcol8 = (lane >> 4) << 3;
    const int g = lane >> 2, tq = lane & 3;
    const int z = blockIdx.z;
    const __half* Bg = (z == 0) ? W0 : (z == 1) ? W1 : W2;
    __half* Ch = (z == 0) ? C0 : (z == 1) ? C1 : C2;
    const bool dorope = (z < 2);

    float acc[4][8][4];
#pragma unroll
    for (int i = 0; i < 4; i++)
#pragma unroll
        for (int j = 0; j < 8; j++)
#pragma unroll
            for (int e = 0; e < 4; e++) acc[i][j][e] = 0.f;

    gemm_main(acc, Ag, Bg, m0, n0, sm, tid, wm, wn, lrow, lcol8);

#pragma unroll
    for (int mt = 0; mt < 4; mt++)
#pragma unroll
        for (int nt = 0; nt < 8; nt++) {
            const int row0 = m0 + wm * 64 + mt * 16 + g;
            const int col  = n0 + wn * 64 + nt * 8 + tq * 2;
            if (dorope) {
                const int i = (col & (HD_ - 1)) >> 1;
#pragma unroll
                for (int half = 0; half < 2; half++) {
                    const int row = row0 + half * 8;
                    const int s = row & (S_ - 1);
                    const float c = fc[s * (HD_/2) + i];
                    const float sn = fs[s * (HD_/2) + i];
                    const float x0 = acc[mt][nt][2*half], x1 = acc[mt][nt][2*half+1];
                    *(uint32_t*)(Ch + (size_t)row * D_ + col) =
                        pack_h2(x0 * c - x1 * sn, x0 * sn + x1 * c);
                }
            } else {
                *(uint32_t*)(Ch + (size_t)row0 * D_ + col) =
                    pack_h2(acc[mt][nt][0], acc[mt][nt][1]);
                *(uint32_t*)(Ch + (size_t)(row0 + 8) * D_ + col) =
                    pack_h2(acc[mt][nt][2], acc[mt][nt][3]);
            }
        }
}

// ---- output-projection GEMM: fp32 C ----
__global__ __launch_bounds__(GT, 2)
void gemm_out(const __half* __restrict__ Ag, const __half* __restrict__ Bg,
              float* __restrict__ C) {
    extern __shared__ __align__(16) __half sm[];
    const int tid = threadIdx.x;
    const int wid = tid >> 5, lane = tid & 31;
    const int wm = wid >> 1, wn = wid & 1;
    const int m0 = blockIdx.x * GBM, n0 = blockIdx.y * GBN;
    const int lrow = lane & 15, lcol8 = (lane >> 4) << 3;
    const int g = lane >> 2, tq = lane & 3;

    float acc[4][8][4];
#pragma unroll
    for (int i = 0; i < 4; i++)
#pragma unroll
        for (int j = 0; j < 8; j++)
#pragma unroll
            for (int e = 0; e < 4; e++) acc[i][j][e] = 0.f;

    gemm_main(acc, Ag, Bg, m0, n0, sm, tid, wm, wn, lrow, lcol8);

#pragma unroll
    for (int mt = 0; mt < 4; mt++)
#pragma unroll
        for (int nt = 0; nt < 8; nt++) {
            const int row0 = m0 + wm * 64 + mt * 16 + g;
            const int col  = n0 + wn * 64 + nt * 8 + tq * 2;
            *(float2*)(C + (size_t)row0 * D_ + col) =
                make_float2(acc[mt][nt][0], acc[mt][nt][1]);
            *(float2*)(C + (size_t)(row0 + 8) * D_ + col) =
                make_float2(acc[mt][nt][2], acc[mt][nt][3]);
        }
}

// ---------------- flash attention (exp2-domain softmax + hoisted Q frags) ----------------
#define ALD 136
#define AQ_ELEMS (128 * ALD)
#define AKV_ELEMS (64 * ALD)
#define ATTN_SMEM ((AQ_ELEMS + 2 * 2 * AKV_ELEMS) * 2)   // 104448 B

__global__ __launch_bounds__(256, 1)
void attn_kernel(const __half* __restrict__ Q, const __half* __restrict__ Kg,
                 const __half* __restrict__ Vg, __half* __restrict__ O) {
    extern __shared__ __align__(16) __half smn[];
    __half* sQ = smn;
    __half* sKV = sQ + AQ_ELEMS;

    const int tid = threadIdx.x;
    const int wid = tid >> 5, lane = tid & 31;
    const int g = lane >> 2, tq = lane & 3;
    const int qt = (int)gridDim.x - 1 - (int)blockIdx.x;
    const int h = blockIdx.y, b = blockIdx.z;
    const int lrow = lane & 15, lcol8 = (lane >> 4) << 3;
    // scale * log2(e): softmax done in base-2 domain
    const float scale2 = 0.12751743342f;

    auto load_kv = [&](int j, int buf) {
        __half* base = sKV + buf * 2 * AKV_ELEMS;
#pragma unroll
        for (int p = 0; p < 8; p++) {
            int c = tid + p * 256;
            int arr = c >> 10;
            int idx = c & 1023;
            int row = idx >> 4;
            int col8 = (idx & 15) << 3;
            size_t goff = ((size_t)(b * S_ + j * 64 + row)) * D_ + h * HD_ + col8;
            cp16(base + arr * AKV_ELEMS + row * ALD + col8, (arr ? Vg : Kg) + goff);
        }
    };

    {
#pragma unroll
        for (int p = 0; p < 8; p++) {
            int c = tid + p * 256;
            int row = c >> 4;
            int col8 = (c & 15) << 3;
            size_t goff = ((size_t)(b * S_ + qt * 128 + row)) * D_ + h * HD_ + col8;
            cp16(sQ + row * ALD + col8, Q + goff);
        }
    }
    load_kv(0, 0);
    cp_commit();

    float oacc[16][4];
#pragma unroll
    for (int i = 0; i < 16; i++)
#pragma unroll
        for (int e = 0; e < 4; e++) oacc[i][e] = 0.f;
    float sm2[2] = {-1e30f, -1e30f};
    float sl2[2] = {0.f, 0.f};

    uint32_t qfa[8][4];                 // persistent Q fragments (loaded at j=0)
    const int qrow = wid * 16 + lrow;
    const int jmax = 2 * qt + 1;
    for (int j = 0; j <= jmax; ++j) {
        cp_wait<0>();
        __syncthreads();
        if (j == 0) {
#pragma unroll
            for (int kc = 0; kc < 8; kc++)
                ldm_x4(qfa[kc][0], qfa[kc][1], qfa[kc][2], qfa[kc][3],
                       smem_u32(sQ + qrow * ALD + kc * 16 + lcol8));
        }
        if (j + 1 <= jmax) load_kv(j + 1, (j + 1) & 1);
        cp_commit();

        const __half* sK = sKV + (j & 1) * 2 * AKV_ELEMS;
        const __half* sV = sK + AKV_ELEMS;

        // ---- S = Q K^T (K fragments double-buffered, Q from registers) ----
        float sacc[8][4];
#pragma unroll
        for (int i = 0; i < 8; i++)
#pragma unroll
            for (int e = 0; e < 4; e++) sacc[i][e] = 0.f;

        uint32_t kr[2][4];
        ldm_x4(kr[0][0], kr[0][1], kr[0][2], kr[0][3],
               smem_u32(sK + lrow * ALD + lcol8));

#pragma unroll
        for (int kc = 0; kc < 8; kc++) {
#pragma unroll
            for (int nt2 = 0; nt2 < 4; nt2++) {
                const int s = kc * 4 + nt2;
                const int cur = s & 1, alt = cur ^ 1;
                if (s < 31) {
                    const int ns = s + 1, nkc = ns >> 2, nnt2 = ns & 3;
                    ldm_x4(kr[alt][0], kr[alt][1], kr[alt][2], kr[alt][3],
                           smem_u32(sK + (nnt2 * 16 + lrow) * ALD + nkc * 16 + lcol8));
                }
                uint32_t b0[2] = {kr[cur][0], kr[cur][2]};
                uint32_t b1[2] = {kr[cur][1], kr[cur][3]};
                mma_f16(sacc[2*nt2], qfa[kc], b0);
                mma_f16(sacc[2*nt2+1], qfa[kc], b1);
            }
        }

        // ---- scale (base-2) + causal mask + online softmax ----
        const int qg0 = qt * 128 + wid * 16 + g;
        const bool need_mask = (j >= 2 * qt);
        float mx0 = -1e30f, mx1 = -1e30f;
#pragma unroll
        for (int nt = 0; nt < 8; nt++) {
            int kg = j * 64 + nt * 8 + tq * 2;
#pragma unroll
            for (int e = 0; e < 4; e++) {
                float sv = sacc[nt][e] * scale2;
                int row = (e < 2) ? qg0 : (qg0 + 8);
                int col = kg + (e & 1);
                if (need_mask && col > row) sv = -1e30f;
                sacc[nt][e] = sv;
                if (e < 2) mx0 = fmaxf(mx0, sv); else mx1 = fmaxf(mx1, sv);
            }
        }
        mx0 = fmaxf(mx0, __shfl_xor_sync(0xffffffffu, mx0, 1));
        mx0 = fmaxf(mx0, __shfl_xor_sync(0xffffffffu, mx0, 2));
        mx1 = fmaxf(mx1, __shfl_xor_sync(0xffffffffu, mx1, 1));
        mx1 = fmaxf(mx1, __shfl_xor_sync(0xffffffffu, mx1, 2));

        float mn0 = fmaxf(sm2[0], mx0), mn1 = fmaxf(sm2[1], mx1);
        float al0 = exp2f(sm2[0] - mn0), al1 = exp2f(sm2[1] - mn1);
        sm2[0] = mn0; sm2[1] = mn1;

        float rs0 = 0.f, rs1 = 0.f;
#pragma unroll
        for (int nt = 0; nt < 8; nt++)
#pragma unroll
            for (int e = 0; e < 4; e++) {
                float pv = exp2f(sacc[nt][e] - ((e < 2) ? mn0 : mn1));
                sacc[nt][e] = pv;
                if (e < 2) rs0 += pv; else rs1 += pv;
            }
        rs0 += __shfl_xor_sync(0xffffffffu, rs0, 1);
        rs0 += __shfl_xor_sync(0xffffffffu, rs0, 2);
        rs1 += __shfl_xor_sync(0xffffffffu, rs1, 1);
        rs1 += __shfl_xor_sync(0xffffffffu, rs1, 2);
        sl2[0] = sl2[0] * al0 + rs0;
        sl2[1] = sl2[1] * al1 + rs1;

#pragma unroll
        for (int dt = 0; dt < 16; dt++) {
            oacc[dt][0] *= al0; oacc[dt][1] *= al0;
            oacc[dt][2] *= al1; oacc[dt][3] *= al1;
        }

        // ---- O += P V (V fragments double-buffered) ----
        uint32_t pf[4][4];
#pragma unroll
        for (int kc = 0; kc < 4; kc++) {
            pf[kc][0] = pack_h2(sacc[2*kc][0],   sacc[2*kc][1]);
            pf[kc][1] = pack_h2(sacc[2*kc][2],   sacc[2*kc][3]);
            pf[kc][2] = pack_h2(sacc[2*kc+1][0], sacc[2*kc+1][1]);
            pf[kc][3] = pack_h2(sacc[2*kc+1][2], sacc[2*kc+1][3]);
        }

        uint32_t vr[2][4];
        ldm_x4_t(vr[0][0], vr[0][1], vr[0][2], vr[0][3],
                 smem_u32(sV + lrow * ALD + lcol8));
#pragma unroll
        for (int s = 0; s < 32; s++) {
            const int kc = s >> 3, dt2 = s & 7;
            const int cur = s & 1, alt = cur ^ 1;
            if (s < 31) {
                const int ns = s + 1, nkc = ns >> 3, ndt2 = ns & 7;
                ldm_x4_t(vr[alt][0], vr[alt][1], vr[alt][2], vr[alt][3],
                         smem_u32(sV + (nkc * 16 + lrow) * ALD + ndt2 * 16 + lcol8));
            }
            uint32_t v0[2] = {vr[cur][0], vr[cur][1]};
            uint32_t v1[2] = {vr[cur][2], vr[cur][3]};
            mma_f16(oacc[2*dt2], pf[kc], v0);
            mma_f16(oacc[2*dt2+1], pf[kc], v1);
        }
    }

    float inv0 = 1.f / sl2[0];
    float inv1 = 1.f / sl2[1];
    int s0r = qt * 128 + wid * 16 + g;
#pragma unroll
    for (int dt = 0; dt < 16; dt++) {
        int col = h * HD_ + dt * 8 + tq * 2;
        *(uint32_t*)(O + ((size_t)(b * S_ + s0r)) * D_ + col) =
            pack_h2(oacc[dt][0] * inv0, oacc[dt][1] * inv0);
        *(uint32_t*)(O + ((size_t)(b * S_ + s0r + 8)) * D_ + col) =
            pack_h2(oacc[dt][2] * inv1, oacc[dt][3] * inv1);
    }
}

// ---------------- launch ----------------
extern "C" void kernel_launch(void* const* d_in, const int* in_sizes, int n_in,
                              void* d_out, int out_size) {
    const float* x  = (const float*)d_in[0];
    const float* fc = (const float*)d_in[1];
    const float* fs = (const float*)d_in[2];
    const float* wq = (const float*)d_in[4];
    const float* wk = (const float*)d_in[5];
    const float* wv = (const float*)d_in[6];
    const float* wo = (const float*)d_in[7];
    float* out = (float*)d_out;

    __half *xh, *wqh, *wkh, *wvh, *woh, *qh, *kh, *vh, *ah;
    cudaGetSymbolAddress((void**)&xh, g_x);
    cudaGetSymbolAddress((void**)&wqh, g_wq);
    cudaGetSymbolAddress((void**)&wkh, g_wk);
    cudaGetSymbolAddress((void**)&wvh, g_wv);
    cudaGetSymbolAddress((void**)&woh, g_wo);
    cudaGetSymbolAddress((void**)&qh, g_q);
    cudaGetSymbolAddress((void**)&kh, g_k);
    cudaGetSymbolAddress((void**)&vh, g_v);
    cudaGetSymbolAddress((void**)&ah, g_a);

    const int n4 = (int)(NELEM / 4);
    const int cvt_blocks = (n4 / CVT_PER_THREAD + 255) / 256;
    cvt_h5<<<dim3(cvt_blocks, 5), 256>>>(
        (const float4*)x, (const float4*)wq, (const float4*)wk,
        (const float4*)wv, (const float4*)wo,
        (uint2*)xh, (uint2*)wqh, (uint2*)wkh, (uint2*)wvh, (uint2*)woh, n4);

    cudaFuncSetAttribute(qkv_gemm, cudaFuncAttributeMaxDynamicSharedMemorySize, GEMM_SMEM);
    cudaFuncSetAttribute(gemm_out, cudaFuncAttributeMaxDynamicSharedMemorySize, GEMM_SMEM);

    dim3 gq(MTOK / GBM, D_ / GBN, 3);   // (32, 32, 3)
    qkv_gemm<<<gq, GT, GEMM_SMEM>>>(xh, wqh, wkh, wvh, qh, kh, vh, fc, fs);

    cudaFuncSetAttribute(attn_kernel, cudaFuncAttributeMaxDynamicSharedMemorySize, ATTN_SMEM);
    attn_kernel<<<dim3(S_ / 128, H_, B_), 256, ATTN_SMEM>>>(qh, kh, vh, ah);

    dim3 gg(MTOK / GBM, D_ / GBN);      // (32, 32)
    gemm_out<<<gg, GT, GEMM_SMEM>>>(ah, woh, out);
}

// round 16
// speedup vs baseline: 1.0222x; 1.0091x over previous
#include <cuda_runtime.h>
#include <cuda_fp16.h>
#include <cstdint>

#define B_  2
#define S_  2048
#define D_  4096
#define H_  32
#define HD_ 128
#define MTOK (B_*S_)
#define NELEM ((size_t)MTOK * D_)

// ---------------- scratch (allocation-free) ----------------
__device__ __half g_x[NELEM];
__device__ __half g_wq[NELEM], g_wk[NELEM], g_wv[NELEM], g_wo[NELEM];
__device__ __half g_q[NELEM], g_k[NELEM], g_v[NELEM], g_a[NELEM];

// ---------------- helpers ----------------
__device__ __forceinline__ uint32_t smem_u32(const void* p) {
    return (uint32_t)__cvta_generic_to_shared(p);
}
__device__ __forceinline__ void cp16(void* dst, const void* src) {
    asm volatile("cp.async.cg.shared.global [%0], [%1], 16;"
                 :: "r"(smem_u32(dst)), "l"(src) : "memory");
}
__device__ __forceinline__ void cp_commit() {
    asm volatile("cp.async.commit_group;" ::: "memory");
}
template<int N>
__device__ __forceinline__ void cp_wait() {
    asm volatile("cp.async.wait_group %0;" :: "n"(N) : "memory");
}
__device__ __forceinline__ void ldm_x4(uint32_t& r0, uint32_t& r1, uint32_t& r2, uint32_t& r3, uint32_t addr) {
    asm volatile("ldmatrix.sync.aligned.m8n8.x4.shared.b16 {%0,%1,%2,%3}, [%4];"
                 : "=r"(r0), "=r"(r1), "=r"(r2), "=r"(r3) : "r"(addr));
}
__device__ __forceinline__ void ldm_x4_t(uint32_t& r0, uint32_t& r1, uint32_t& r2, uint32_t& r3, uint32_t addr) {
    asm volatile("ldmatrix.sync.aligned.m8n8.x4.trans.shared.b16 {%0,%1,%2,%3}, [%4];"
                 : "=r"(r0), "=r"(r1), "=r"(r2), "=r"(r3) : "r"(addr));
}
__device__ __forceinline__ void mma_f16(float* c, const uint32_t* a, const uint32_t* b) {
    asm volatile(
        "mma.sync.aligned.m16n8k16.row.col.f32.f16.f16.f32 "
        "{%0,%1,%2,%3}, {%4,%5,%6,%7}, {%8,%9}, {%0,%1,%2,%3};"
        : "+f"(c[0]), "+f"(c[1]), "+f"(c[2]), "+f"(c[3])
        : "r"(a[0]), "r"(a[1]), "r"(a[2]), "r"(a[3]), "r"(b[0]), "r"(b[1]));
}
__device__ __forceinline__ uint32_t pack_h2(float a, float b) {
    __half2 h = __floats2half2_rn(a, b);
    return *(uint32_t*)&h;
}

// ---------------- convert: fp32 -> fp16, 5 tensors, 4 chunks/thread (MLP=4) ----------------
#define CVT_PER_THREAD 4
__global__ void cvt_h5(const float4* __restrict__ s0, const float4* __restrict__ s1,
                       const float4* __restrict__ s2, const float4* __restrict__ s3,
                       const float4* __restrict__ s4,
                       uint2* __restrict__ d0, uint2* __restrict__ d1,
                       uint2* __restrict__ d2, uint2* __restrict__ d3,
                       uint2* __restrict__ d4, int n4) {
    const int stride = (int)gridDim.x * (int)blockDim.x;
    const int base = blockIdx.x * blockDim.x + threadIdx.x;
    const int z = blockIdx.y;
    const float4* s = (z == 0) ? s0 : (z == 1) ? s1 : (z == 2) ? s2 : (z == 3) ? s3 : s4;
    uint2* d = (z == 0) ? d0 : (z == 1) ? d1 : (z == 2) ? d2 : (z == 3) ? d3 : d4;

    float4 v[CVT_PER_THREAD];
#pragma unroll
    for (int p = 0; p < CVT_PER_THREAD; p++) {
        const int i = base + p * stride;
        if (i < n4) v[p] = s[i];
    }
#pragma unroll
    for (int p = 0; p < CVT_PER_THREAD; p++) {
        const int i = base + p * stride;
        if (i < n4) d[i] = make_uint2(pack_h2(v[p].x, v[p].y), pack_h2(v[p].z, v[p].w));
    }
}

// ============ GEMM: 128x128x32 CTA tile, 4 warps, warp tile 64x64, frag-pipelined ============
// (round-13 configuration, verbatim — FROZEN)
#define GBM 128
#define GBN 128
#define GBK 32
#define GLD 40
#define SA_ELEMS (GBM * GLD)          // 5120 halves
#define STAGE_ELEMS (2 * SA_ELEMS)    // 20KB
#define GEMM_SMEM (4 * STAGE_ELEMS * 2)   // 80KB
#define GT 128

__device__ __forceinline__ void ldm_frags(
    const __half* sA, const __half* sB, int wm, int wn, int lrow, int lcol8,
    int kc, uint32_t a[4][4], uint32_t b[8][2]) {
    const int col = kc * 16 + lcol8;
#pragma unroll
    for (int mt = 0; mt < 4; mt++) {
        const int row = wm * 64 + mt * 16 + lrow;
        ldm_x4(a[mt][0], a[mt][1], a[mt][2], a[mt][3],
               smem_u32(sA + row * GLD + col));
    }
#pragma unroll
    for (int nt2 = 0; nt2 < 4; nt2++) {
        const int row = wn * 64 + nt2 * 16 + lrow;
        uint32_t r0, r1, r2, r3;
        ldm_x4(r0, r1, r2, r3, smem_u32(sB + row * GLD + col));
        b[2*nt2][0] = r0; b[2*nt2][1] = r2;
        b[2*nt2+1][0] = r1; b[2*nt2+1][1] = r3;
    }
}

__device__ __forceinline__ void gemm_main(
    float acc[4][8][4], const __half* __restrict__ Ag, const __half* __restrict__ Bg,
    int m0, int n0, __half* sm, int tid, int wm, int wn, int lrow, int lcol8) {

    auto load_stage = [&](int kb, int buf) {
        __half* base = sm + buf * STAGE_ELEMS;
        const int k0 = kb * GBK;
#pragma unroll
        for (int p = 0; p < 8; p++) {
            const int t = tid + p * GT;
            const int arr = t >> 9;
            const int i = t & 511;
            const int row = i >> 2, col8 = (i & 3) << 3;
            const __half* gsrc = (arr ? Bg : Ag) + (size_t)((arr ? n0 : m0) + row) * D_ + k0 + col8;
            cp16(base + arr * SA_ELEMS + row * GLD + col8, gsrc);
        }
    };

    const int KT = D_ / GBK;           // 128
    load_stage(0, 0); cp_commit();
    load_stage(1, 1); cp_commit();
    load_stage(2, 2); cp_commit();
    cp_wait<1>();
    __syncthreads();

    uint32_t a0[4][4], b0[8][2], a1[4][4], b1[8][2];
    ldm_frags(sm, sm + SA_ELEMS, wm, wn, lrow, lcol8, 0, a0, b0);

    for (int kb = 0; kb < KT; kb++) {
        const __half* sA = sm + (kb & 3) * STAGE_ELEMS;
        const __half* sB = sA + SA_ELEMS;
        if (kb + 3 < KT) load_stage(kb + 3, (kb + 3) & 3);
        cp_commit();

        ldm_frags(sA, sB, wm, wn, lrow, lcol8, 1, a1, b1);

#pragma unroll
        for (int mt = 0; mt < 4; mt++)
#pragma unroll
            for (int nt = 0; nt < 8; nt++)
                mma_f16(acc[mt][nt], a0[mt], b0[nt]);

        if (kb + 1 < KT) {
            const __half* nA = sm + ((kb + 1) & 3) * STAGE_ELEMS;
            ldm_frags(nA, nA + SA_ELEMS, wm, wn, lrow, lcol8, 0, a0, b0);
        }

#pragma unroll
        for (int mt = 0; mt < 4; mt++)
#pragma unroll
            for (int nt = 0; nt < 8; nt++)
                mma_f16(acc[mt][nt], a1[mt], b1[nt]);

        cp_wait<1>();
        __syncthreads();
    }
}

// ---- fused QKV GEMM: z=0 -> q (rope), z=1 -> k (rope), z=2 -> v (plain fp16) ----
__global__ __launch_bounds__(GT, 2)
void qkv_gemm(const __half* __restrict__ Ag,
              const __half* __restrict__ W0, const __half* __restrict__ W1,
              const __half* __restrict__ W2,
              __half* __restrict__ C0, __half* __restrict__ C1, __half* __restrict__ C2,
              const float* __restrict__ fc, const float* __restrict__ fs) {
    extern __shared__ __align__(16) __half sm[];
    const int tid = threadIdx.x;
    const int wid = tid >> 5, lane = tid & 31;
    const int wm = wid >> 1, wn = wid & 1;
    const int m0 = blockIdx.x * GBM, n0 = blockIdx.y * GBN;
    const int lrow = lane & 15, lcol8 = (lane >> 4) << 3;
    const int g = lane >> 2, tq = lane & 3;
    const int z = blockIdx.z;
    const __half* Bg = (z == 0) ? W0 : (z == 1) ? W1 : W2;
    __half* Ch = (z == 0) ? C0 : (z == 1) ? C1 : C2;
    const bool dorope = (z < 2);

    float acc[4][8][4];
#pragma unroll
    for (int i = 0; i < 4; i++)
#pragma unroll
        for (int j = 0; j < 8; j++)
#pragma unroll
            for (int e = 0; e < 4; e++) acc[i][j][e] = 0.f;

    gemm_main(acc, Ag, Bg, m0, n0, sm, tid, wm, wn, lrow, lcol8);

#pragma unroll
    for (int mt = 0; mt < 4; mt++)
#pragma unroll
        for (int nt = 0; nt < 8; nt++) {
            const int row0 = m0 + wm * 64 + mt * 16 + g;
            const int col  = n0 + wn * 64 + nt * 8 + tq * 2;
            if (dorope) {
                const int i = (col & (HD_ - 1)) >> 1;
#pragma unroll
                for (int half = 0; half < 2; half++) {
                    const int row = row0 + half * 8;
                    const int s = row & (S_ - 1);
                    const float c = fc[s * (HD_/2) + i];
                    const float sn = fs[s * (HD_/2) + i];
                    const float x0 = acc[mt][nt][2*half], x1 = acc[mt][nt][2*half+1];
                    *(uint32_t*)(Ch + (size_t)row * D_ + col) =
                        pack_h2(x0 * c - x1 * sn, x0 * sn + x1 * c);
                }
            } else {
                *(uint32_t*)(Ch + (size_t)row0 * D_ + col) =
                    pack_h2(acc[mt][nt][0], acc[mt][nt][1]);
                *(uint32_t*)(Ch + (size_t)(row0 + 8) * D_ + col) =
                    pack_h2(acc[mt][nt][2], acc[mt][nt][3]);
            }
        }
}

// ---- output-projection GEMM: fp32 C ----
__global__ __launch_bounds__(GT, 2)
void gemm_out(const __half* __restrict__ Ag, const __half* __restrict__ Bg,
              float* __restrict__ C) {
    extern __shared__ __align__(16) __half sm[];
    const int tid = threadIdx.x;
    const int wid = tid >> 5, lane = tid & 31;
    const int wm = wid >> 1, wn = wid & 1;
    const int m0 = blockIdx.x * GBM, n0 = blockIdx.y * GBN;
    const int lrow = lane & 15, lcol8 = (lane >> 4) << 3;
    const int g = lane >> 2, tq = lane & 3;

    float acc[4][8][4];
#pragma unroll
    for (int i = 0; i < 4; i++)
#pragma unroll
        for (int j = 0; j < 8; j++)
#pragma unroll
            for (int e = 0; e < 4; e++) acc[i][j][e] = 0.f;

    gemm_main(acc, Ag, Bg, m0, n0, sm, tid, wm, wn, lrow, lcol8);

#pragma unroll
    for (int mt = 0; mt < 4; mt++)
#pragma unroll
        for (int nt = 0; nt < 8; nt++) {
            const int row0 = m0 + wm * 64 + mt * 16 + g;
            const int col  = n0 + wn * 64 + nt * 8 + tq * 2;
            *(float2*)(C + (size_t)row0 * D_ + col) =
                make_float2(acc[mt][nt][0], acc[mt][nt][1]);
            *(float2*)(C + (size_t)(row0 + 8) * D_ + col) =
                make_float2(acc[mt][nt][2], acc[mt][nt][3]);
        }
}

// ---------------- flash attention: 128-row KV tiles (halved per-tile overhead) ----------------
#define ALD 136
#define AQ_ELEMS (128 * ALD)
#define AKV_ELEMS (128 * ALD)
#define ATTN_SMEM ((AQ_ELEMS + 2 * 2 * AKV_ELEMS) * 2)   // 174080 B

__global__ __launch_bounds__(256, 1)
void attn_kernel(const __half* __restrict__ Q, const __half* __restrict__ Kg,
                 const __half* __restrict__ Vg, __half* __restrict__ O) {
    extern __shared__ __align__(16) __half smn[];
    __half* sQ = smn;
    __half* sKV = sQ + AQ_ELEMS;

    const int tid = threadIdx.x;
    const int wid = tid >> 5, lane = tid & 31;
    const int g = lane >> 2, tq = lane & 3;
    const int qt = (int)gridDim.x - 1 - (int)blockIdx.x;   // heavy CTAs first
    const int h = blockIdx.y, b = blockIdx.z;
    const int lrow = lane & 15, lcol8 = (lane >> 4) << 3;
    const float scale2 = 0.12751743342f;   // scale * log2(e)

    auto load_kv = [&](int j, int buf) {
        __half* base = sKV + buf * 2 * AKV_ELEMS;
#pragma unroll
        for (int p = 0; p < 16; p++) {
            int c = tid + p * 256;           // 0..4095
            int arr = c >> 11;               // 0=K, 1=V
            int idx = c & 2047;
            int row = idx >> 4;
            int col8 = (idx & 15) << 3;
            size_t goff = ((size_t)(b * S_ + j * 128 + row)) * D_ + h * HD_ + col8;
            cp16(base + arr * AKV_ELEMS + row * ALD + col8, (arr ? Vg : Kg) + goff);
        }
    };

    {
#pragma unroll
        for (int p = 0; p < 8; p++) {
            int c = tid + p * 256;
            int row = c >> 4;
            int col8 = (c & 15) << 3;
            size_t goff = ((size_t)(b * S_ + qt * 128 + row)) * D_ + h * HD_ + col8;
            cp16(sQ + row * ALD + col8, Q + goff);
        }
    }
    load_kv(0, 0);
    cp_commit();

    float oacc[16][4];
#pragma unroll
    for (int i = 0; i < 16; i++)
#pragma unroll
        for (int e = 0; e < 4; e++) oacc[i][e] = 0.f;
    float sm2[2] = {-1e30f, -1e30f};
    float sl2[2] = {0.f, 0.f};

    const int qrow = wid * 16 + lrow;
    const int jmax = qt;                      // 128-row KV tiles: j = 0..qt
    for (int j = 0; j <= jmax; ++j) {
        cp_wait<0>();
        __syncthreads();
        if (j + 1 <= jmax) load_kv(j + 1, (j + 1) & 1);
        cp_commit();

        const __half* sK = sKV + (j & 1) * 2 * AKV_ELEMS;
        const __half* sV = sK + AKV_ELEMS;

        // ---- S = Q K^T  (16 q-rows x 128 kv per warp) ----
        float sacc[16][4];
#pragma unroll
        for (int i = 0; i < 16; i++)
#pragma unroll
            for (int e = 0; e < 4; e++) sacc[i][e] = 0.f;

        uint32_t qf[2][4], kr[2][4];
        ldm_x4(qf[0][0], qf[0][1], qf[0][2], qf[0][3],
               smem_u32(sQ + qrow * ALD + lcol8));
        ldm_x4(kr[0][0], kr[0][1], kr[0][2], kr[0][3],
               smem_u32(sK + lrow * ALD + lcol8));

#pragma unroll
        for (int kc = 0; kc < 8; kc++) {
            const int cq = kc & 1;
#pragma unroll
            for (int nt2 = 0; nt2 < 8; nt2++) {
                const int s = kc * 8 + nt2;
                const int cur = s & 1, alt = cur ^ 1;
                if (s < 63) {
                    const int ns = s + 1, nkc = ns >> 3, nnt2 = ns & 7;
                    ldm_x4(kr[alt][0], kr[alt][1], kr[alt][2], kr[alt][3],
                           smem_u32(sK + (nnt2 * 16 + lrow) * ALD + nkc * 16 + lcol8));
                }
                if (nt2 == 7 && kc < 7) {
                    ldm_x4(qf[cq ^ 1][0], qf[cq ^ 1][1], qf[cq ^ 1][2], qf[cq ^ 1][3],
                           smem_u32(sQ + qrow * ALD + (kc + 1) * 16 + lcol8));
                }
                uint32_t b0[2] = {kr[cur][0], kr[cur][2]};
                uint32_t b1[2] = {kr[cur][1], kr[cur][3]};
                mma_f16(sacc[2*nt2], qf[cq], b0);
                mma_f16(sacc[2*nt2+1], qf[cq], b1);
            }
        }

        // ---- scale (base-2) + causal mask + online softmax ----
        const int qg0 = qt * 128 + wid * 16 + g;
        const bool need_mask = (j == qt);
        float mx0 = -1e30f, mx1 = -1e30f;
#pragma unroll
        for (int nt = 0; nt < 16; nt++) {
            int kg = j * 128 + nt * 8 + tq * 2;
#pragma unroll
            for (int e = 0; e < 4; e++) {
                float sv = sacc[nt][e] * scale2;
                int row = (e < 2) ? qg0 : (qg0 + 8);
                int col = kg + (e & 1);
                if (need_mask && col > row) sv = -1e30f;
                sacc[nt][e] = sv;
                if (e < 2) mx0 = fmaxf(mx0, sv); else mx1 = fmaxf(mx1, sv);
            }
        }
        mx0 = fmaxf(mx0, __shfl_xor_sync(0xffffffffu, mx0, 1));
        mx0 = fmaxf(mx0, __shfl_xor_sync(0xffffffffu, mx0, 2));
        mx1 = fmaxf(mx1, __shfl_xor_sync(0xffffffffu, mx1, 1));
        mx1 = fmaxf(mx1, __shfl_xor_sync(0xffffffffu, mx1, 2));

        float mn0 = fmaxf(sm2[0], mx0), mn1 = fmaxf(sm2[1], mx1);
        float al0 = exp2f(sm2[0] - mn0), al1 = exp2f(sm2[1] - mn1);
        sm2[0] = mn0; sm2[1] = mn1;

        float rs0 = 0.f, rs1 = 0.f;
#pragma unroll
        for (int nt = 0; nt < 16; nt++)
#pragma unroll
            for (int e = 0; e < 4; e++) {
                float pv = exp2f(sacc[nt][e] - ((e < 2) ? mn0 : mn1));
                sacc[nt][e] = pv;
                if (e < 2) rs0 += pv; else rs1 += pv;
            }
        rs0 += __shfl_xor_sync(0xffffffffu, rs0, 1);
        rs0 += __shfl_xor_sync(0xffffffffu, rs0, 2);
        rs1 += __shfl_xor_sync(0xffffffffu, rs1, 1);
        rs1 += __shfl_xor_sync(0xffffffffu, rs1, 2);
        sl2[0] = sl2[0] * al0 + rs0;
        sl2[1] = sl2[1] * al1 + rs1;

#pragma unroll
        for (int dt = 0; dt < 16; dt++) {
            oacc[dt][0] *= al0; oacc[dt][1] *= al0;
            oacc[dt][2] *= al1; oacc[dt][3] *= al1;
        }

        // ---- O += P V (8 k-chunks of 16 KV rows) ----
        uint32_t pf[8][4];
#pragma unroll
        for (int kc = 0; kc < 8; kc++) {
            pf[kc][0] = pack_h2(sacc[2*kc][0],   sacc[2*kc][1]);
            pf[kc][1] = pack_h2(sacc[2*kc][2],   sacc[2*kc][3]);
            pf[kc][2] = pack_h2(sacc[2*kc+1][0], sacc[2*kc+1][1]);
            pf[kc][3] = pack_h2(sacc[2*kc+1][2], sacc[2*kc+1][3]);
        }

        uint32_t vr[2][4];
        ldm_x4_t(vr[0][0], vr[0][1], vr[0][2], vr[0][3],
                 smem_u32(sV + lrow * ALD + lcol8));
#pragma unroll
        for (int s = 0; s < 64; s++) {
            const int kc = s >> 3, dt2 = s & 7;
            const int cur = s & 1, alt = cur ^ 1;
            if (s < 63) {
                const int ns = s + 1, nkc = ns >> 3, ndt2 = ns & 7;
                ldm_x4_t(vr[alt][0], vr[alt][1], vr[alt][2], vr[alt][3],
                         smem_u32(sV + (nkc * 16 + lrow) * ALD + ndt2 * 16 + lcol8));
            }
            uint32_t v0[2] = {vr[cur][0], vr[cur][1]};
            uint32_t v1[2] = {vr[cur][2], vr[cur][3]};
            mma_f16(oacc[2*dt2], pf[kc], v0);
            mma_f16(oacc[2*dt2+1], pf[kc], v1);
        }
    }

    float inv0 = 1.f / sl2[0];
    float inv1 = 1.f / sl2[1];
    int s0r = qt * 128 + wid * 16 + g;
#pragma unroll
    for (int dt = 0; dt < 16; dt++) {
        int col = h * HD_ + dt * 8 + tq * 2;
        *(uint32_t*)(O + ((size_t)(b * S_ + s0r)) * D_ + col) =
            pack_h2(oacc[dt][0] * inv0, oacc[dt][1] * inv0);
        *(uint32_t*)(O + ((size_t)(b * S_ + s0r + 8)) * D_ + col) =
            pack_h2(oacc[dt][2] * inv1, oacc[dt][3] * inv1);
    }
}

// ---------------- launch ----------------
extern "C" void kernel_launch(void* const* d_in, const int* in_sizes, int n_in,
                              void* d_out, int out_size) {
    const float* x  = (const float*)d_in[0];
    const float* fc = (const float*)d_in[1];
    const float* fs = (const float*)d_in[2];
    const float* wq = (const float*)d_in[4];
    const float* wk = (const float*)d_in[5];
    const float* wv = (const float*)d_in[6];
    const float* wo = (const float*)d_in[7];
    float* out = (float*)d_out;

    __half *xh, *wqh, *wkh, *wvh, *woh, *qh, *kh, *vh, *ah;
    cudaGetSymbolAddress((void**)&xh, g_x);
    cudaGetSymbolAddress((void**)&wqh, g_wq);
    cudaGetSymbolAddress((void**)&wkh, g_wk);
    cudaGetSymbolAddress((void**)&wvh, g_wv);
    cudaGetSymbolAddress((void**)&woh, g_wo);
    cudaGetSymbolAddress((void**)&qh, g_q);
    cudaGetSymbolAddress((void**)&kh, g_k);
    cudaGetSymbolAddress((void**)&vh, g_v);
    cudaGetSymbolAddress((void**)&ah, g_a);

    const int n4 = (int)(NELEM / 4);
    const int cvt_blocks = (n4 / CVT_PER_THREAD + 255) / 256;
    cvt_h5<<<dim3(cvt_blocks, 5), 256>>>(
        (const float4*)x, (const float4*)wq, (const float4*)wk,
        (const float4*)wv, (const float4*)wo,
        (uint2*)xh, (uint2*)wqh, (uint2*)wkh, (uint2*)wvh, (uint2*)woh, n4);

    cudaFuncSetAttribute(qkv_gemm, cudaFuncAttributeMaxDynamicSharedMemorySize, GEMM_SMEM);
    cudaFuncSetAttribute(gemm_out, cudaFuncAttributeMaxDynamicSharedMemorySize, GEMM_SMEM);

    dim3 gq(MTOK / GBM, D_ / GBN, 3);   // (32, 32, 3)
    qkv_gemm<<<gq, GT, GEMM_SMEM>>>(xh, wqh, wkh, wvh, qh, kh, vh, fc, fs);

    cudaFuncSetAttribute(attn_kernel, cudaFuncAttributeMaxDynamicSharedMemorySize, ATTN_SMEM);
    attn_kernel<<<dim3(S_ / 128, H_, B_), 256, ATTN_SMEM>>>(qh, kh, vh, ah);

    dim3 gg(MTOK / GBM, D_ / GBN);      // (32, 32)
    gemm_out<<<gg, GT, GEMM_SMEM>>>(ah, woh, out);
}